// round 11
// baseline (speedup 1.0000x reference)
#include <cuda_runtime.h>
#include <cuda_fp16.h>
#include <math.h>

#define N_NODES 50000
#define N_EDGES 500000
#define FDIM    128
#define NGRAPH  128
#define NCONV   4
#define DEGCAP  64

// ---------------- scratch (device globals; allocation-free) ----------------
__device__ __align__(128) __half g_ha[(size_t)N_NODES * FDIM];
__device__ __align__(128) __half g_hb[(size_t)N_NODES * FDIM];
__device__ __align__(128) __half2 g_w1p[NCONV * 64 * FDIM];  // packed (k/2, n)
__device__ __align__(128) __half2 g_w2p[NCONV * 64 * FDIM];
__device__ __align__(16)  float g_stats[NCONV * 2 * FDIM];
__device__ __align__(16)  float g_pool[NGRAPH * FDIM];
__device__ int g_cnt[N_NODES];
__device__ int g_adj[(size_t)N_NODES * DEGCAP];
__device__ int g_gstart[NGRAPH + 1];

// ---------------- helpers ----------------
__device__ __forceinline__ void mma_f16(float* c, const unsigned* a, const unsigned* b) {
    asm volatile(
        "mma.sync.aligned.m16n8k16.row.col.f32.f16.f16.f32 "
        "{%0,%1,%2,%3}, {%4,%5,%6,%7}, {%8,%9}, {%0,%1,%2,%3};\n"
        : "+f"(c[0]), "+f"(c[1]), "+f"(c[2]), "+f"(c[3])
        : "r"(a[0]), "r"(a[1]), "r"(a[2]), "r"(a[3]),
          "r"(b[0]), "r"(b[1]));
}

// ---------------- init + W->fp16 pack ----------------
__global__ void k_init(const float* __restrict__ Ws1, const float* __restrict__ Ws2) {
    int i = blockIdx.x * blockDim.x + threadIdx.x;
    if (i < N_NODES) g_cnt[i] = 0;
    if (i < NCONV * 2 * FDIM) g_stats[i] = 0.f;
    if (i < NGRAPH * FDIM) g_pool[i] = 0.f;
    if (i < NCONV * 64 * FDIM) {
        int l = i >> 13, rem = i & 8191;
        int kp = rem >> 7, n = rem & 127;
        const float* w1 = Ws1 + l * FDIM * FDIM;
        const float* w2 = Ws2 + l * FDIM * FDIM;
        g_w1p[i] = __floats2half2_rn(w1[(2 * kp) * 128 + n], w1[(2 * kp + 1) * 128 + n]);
        g_w2p[i] = __floats2half2_rn(w2[(2 * kp) * 128 + n], w2[(2 * kp + 1) * 128 + n]);
    }
}

// ---------------- adjacency buckets ----------------
__global__ void k_fillb(const int* __restrict__ ei) {
    int e = blockIdx.x * blockDim.x + threadIdx.x;
    if (e < N_EDGES) {
        int d = ei[N_EDGES + e];
        int pos = atomicAdd(&g_cnt[d], 1);
        if (pos < DEGCAP) g_adj[(size_t)d * DEGCAP + pos] = ei[e];
    }
}

// ---------------- graph segment starts (batch is sorted) ----------------
__global__ void k_gstart(const int* __restrict__ batch) {
    int i = blockIdx.x * blockDim.x + threadIdx.x;
    if (i >= N_NODES) return;
    int b = batch[i];
    int bp = (i == 0) ? -1 : batch[i - 1];
    for (int g = bp + 1; g <= b; g++) g_gstart[g] = i;
    if (i == N_NODES - 1)
        for (int g = b + 1; g <= NGRAPH; g++) g_gstart[g] = N_NODES;
}

// ====== fused layer (fp16): BN-affine + agg + GEMM1+relu + GEMM2+relu + stats ======
// 64-row tile, 256 threads = 8 warps (warp grid 4x2, warp tile 16x64), fp16 MMA k16.
// sA = 64x68 half2 (z, then t1); sB = 32x136 half2 (W chunk); sIdx/sDeg = prefetched
// adjacency (first 16 idx + degree per row). 40.2 KB static, 4 CTAs/SM, 64 regs.
#define SAH 68
#define SBH 136

__global__ __launch_bounds__(256, 4)
void k_layer(const float* __restrict__ xext,
             const float* __restrict__ b1, const float* __restrict__ b2,
             const float* __restrict__ gam, const float* __restrict__ bet,
             int layer) {
    __shared__ __half2 sA2[64 * SAH];
    __shared__ __half2 sB2[32 * SBH];
    __shared__ float sred[2 * FDIM];
    __shared__ int sIdx[64 * 16];
    __shared__ int sDeg[64];

    const __half* hin = (layer & 1) ? g_hb : g_ha;
    __half* hout = (layer & 1) ? g_ha : g_hb;
    const unsigned* sAu = (const unsigned*)sA2;
    const unsigned* sBu = (const unsigned*)sB2;
    const int M = N_NODES;

    int tid = threadIdx.x, wid = tid >> 5, lane = tid & 31;
    int gid = lane >> 2, tig = lane & 3;
    int wm = (wid & 3) * 16, wn = (wid >> 2) * 64;
    int m0 = blockIdx.x * 64;

    sred[tid] = 0.f;

    // ---- cooperative adjacency prefetch: deg + first 16 idx per tile row ----
    {
        int pr = tid >> 2, pq = tid & 3;
        int nd = m0 + pr; if (nd > M - 1) nd = M - 1;
        *(uint4*)(sIdx + pr * 16 + pq * 4) =
            *(const uint4*)(g_adj + (size_t)nd * DEGCAP + pq * 4);
        if (tid < 64) {
            int nd2 = m0 + tid; if (nd2 > M - 1) nd2 = M - 1;
            int d = g_cnt[nd2];
            sDeg[tid] = (d > DEGCAP) ? DEGCAP : d;
        }
    }

    // per-lane BN affine (cols lane*4 .. +3)
    float sc0 = 1.f, sc1 = 1.f, sc2 = 1.f, sc3 = 1.f;
    float sh0 = 0.f, sh1 = 0.f, sh2 = 0.f, sh3 = 0.f;
    if (layer > 0) {
        const float* st = g_stats + (layer - 1) * 2 * FDIM;
        const float invN = 1.f / (float)N_NODES;
        int c = lane * 4;
        float mu0 = st[c] * invN, v0 = fmaxf(st[FDIM + c] * invN - mu0 * mu0, 0.f);
        sc0 = gam[c] * rsqrtf(v0 + 1e-5f); sh0 = bet[c] - mu0 * sc0;
        float mu1 = st[c + 1] * invN, v1 = fmaxf(st[FDIM + c + 1] * invN - mu1 * mu1, 0.f);
        sc1 = gam[c + 1] * rsqrtf(v1 + 1e-5f); sh1 = bet[c + 1] - mu1 * sc1;
        float mu2 = st[c + 2] * invN, v2 = fmaxf(st[FDIM + c + 2] * invN - mu2 * mu2, 0.f);
        sc2 = gam[c + 2] * rsqrtf(v2 + 1e-5f); sh2 = bet[c + 2] - mu2 * sc2;
        float mu3 = st[c + 3] * invN, v3 = fmaxf(st[FDIM + c + 3] * invN - mu3 * mu3, 0.f);
        sc3 = gam[c + 3] * rsqrtf(v3 + 1e-5f); sh3 = bet[c + 3] - mu3 * sc3;
    }
    __syncthreads();

    // ---- aggregation: each warp owns 8 rows; idx from smem, masked 8-wide batches ----
    for (int rr = 0; rr < 8; rr++) {
        int r = wid * 8 + rr;
        int node = m0 + r;
        __half2 o0 = __floats2half2_rn(0.f, 0.f), o1 = o0;
        if (node < M) {
            int deg = sDeg[r];
            const int* sidx = sIdx + r * 16;
            int dm1 = deg - 1;
            float4 acc;
            if (layer == 0) {
                acc = ((const float4*)(xext + (size_t)node * FDIM))[lane];
                for (int k = 0; k < deg; k += 8) {
                    int j[8]; float mk[8];
#pragma unroll
                    for (int u = 0; u < 8; u++) {
                        int idx = k + u;
                        int ic = idx < dm1 ? idx : dm1;
                        j[u] = (k + u < 16) ? sidx[ic < 15 ? ic : 15]
                                            : g_adj[(size_t)node * DEGCAP + ic];
                        mk[u] = (idx < deg) ? 1.f : 0.f;
                    }
                    float4 v[8];
#pragma unroll
                    for (int u = 0; u < 8; u++)
                        v[u] = ((const float4*)(xext + (size_t)j[u] * FDIM))[lane];
#pragma unroll
                    for (int u = 0; u < 8; u++) {
                        acc.x += mk[u] * v[u].x;
                        acc.y += mk[u] * v[u].y;
                        acc.z += mk[u] * v[u].z;
                        acc.w += mk[u] * v[u].w;
                    }
                }
            } else {
                uint2 sv = *(const uint2*)(hin + (size_t)node * FDIM + lane * 4);
                float2 p = __half22float2(*(__half2*)&sv.x);
                float2 q = __half22float2(*(__half2*)&sv.y);
                acc = make_float4(p.x, p.y, q.x, q.y);
                for (int k = 0; k < deg; k += 8) {
                    int j[8]; float mk[8];
#pragma unroll
                    for (int u = 0; u < 8; u++) {
                        int idx = k + u;
                        int ic = idx < dm1 ? idx : dm1;
                        j[u] = (k + u < 16) ? sidx[ic < 15 ? ic : 15]
                                            : g_adj[(size_t)node * DEGCAP + ic];
                        mk[u] = (idx < deg) ? 1.f : 0.f;
                    }
                    uint2 v[8];
#pragma unroll
                    for (int u = 0; u < 8; u++)
                        v[u] = *(const uint2*)(hin + (size_t)j[u] * FDIM + lane * 4);
#pragma unroll
                    for (int u = 0; u < 8; u++) {
                        float2 a = __half22float2(*(__half2*)&v[u].x);
                        float2 b = __half22float2(*(__half2*)&v[u].y);
                        acc.x += mk[u] * a.x;
                        acc.y += mk[u] * a.y;
                        acc.z += mk[u] * b.x;
                        acc.w += mk[u] * b.y;
                    }
                }
                float dp1 = (float)(deg + 1);
                acc.x = sc0 * acc.x + dp1 * sh0;
                acc.y = sc1 * acc.y + dp1 * sh1;
                acc.z = sc2 * acc.z + dp1 * sh2;
                acc.w = sc3 * acc.w + dp1 * sh3;
            }
            o0 = __floats2half2_rn(acc.x, acc.y);
            o1 = __floats2half2_rn(acc.z, acc.w);
        }
        __half2 pair[2] = {o0, o1};
        *(uint2*)(sA2 + r * SAH + lane * 2) = *(uint2*)pair;
    }
    __syncthreads();

    // ---- GEMM1: t1 = z @ W1 ----
    const __half2* wp1 = g_w1p + layer * 64 * FDIM;
    float acc[8][4];
#pragma unroll
    for (int nt = 0; nt < 8; nt++)
#pragma unroll
        for (int i = 0; i < 4; i++) acc[nt][i] = 0.f;

#pragma unroll
    for (int kc = 0; kc < 2; kc++) {
#pragma unroll
        for (int i = 0; i < 4; i++) {
            int slot = tid + i * 256;              // 1024 uint4 slots
            int r = slot >> 5, c4 = (slot & 31) << 2;
            *(uint4*)(sB2 + r * SBH + c4) =
                *(const uint4*)(wp1 + (kc * 32 + r) * FDIM + c4);
        }
        __syncthreads();
#pragma unroll
        for (int kt = 0; kt < 4; kt++) {
            int ak = kc * 32 + kt * 8 + tig;       // half2 k-offset in sA
            int bk = kt * 8 + tig;                 // half2 k-row in sB chunk
            unsigned a[4], b[8][2];
            int r = wm + gid;
            a[0] = sAu[r * SAH + ak];
            a[1] = sAu[(r + 8) * SAH + ak];
            a[2] = sAu[r * SAH + ak + 4];
            a[3] = sAu[(r + 8) * SAH + ak + 4];
#pragma unroll
            for (int nt = 0; nt < 8; nt++) {
                int c = wn + nt * 8 + gid;
                b[nt][0] = sBu[bk * SBH + c];
                b[nt][1] = sBu[(bk + 4) * SBH + c];
            }
#pragma unroll
            for (int nt = 0; nt < 8; nt++)
                mma_f16(acc[nt], a, b[nt]);
        }
        __syncthreads();
    }

    // ---- t1 = relu(acc + b1) back into sA (fp16) ----
#pragma unroll
    for (int nt = 0; nt < 8; nt++) {
        int c0 = wn + nt * 8 + 2 * tig;
        float bb0 = b1[c0], bb1 = b1[c0 + 1];
        int r0 = wm + gid, r1 = r0 + 8;
        int ci = (wn >> 1) + nt * 4 + tig;
        sA2[r0 * SAH + ci] = __floats2half2_rn(fmaxf(acc[nt][0] + bb0, 0.f),
                                               fmaxf(acc[nt][1] + bb1, 0.f));
        sA2[r1 * SAH + ci] = __floats2half2_rn(fmaxf(acc[nt][2] + bb0, 0.f),
                                               fmaxf(acc[nt][3] + bb1, 0.f));
    }
#pragma unroll
    for (int nt = 0; nt < 8; nt++)
#pragma unroll
        for (int i = 0; i < 4; i++) acc[nt][i] = 0.f;

    // ---- GEMM2: t2 = t1 @ W2 (chunk-stage sync covers the sA writes) ----
    const __half2* wp2 = g_w2p + layer * 64 * FDIM;
#pragma unroll
    for (int kc = 0; kc < 2; kc++) {
#pragma unroll
        for (int i = 0; i < 4; i++) {
            int slot = tid + i * 256;
            int r = slot >> 5, c4 = (slot & 31) << 2;
            *(uint4*)(sB2 + r * SBH + c4) =
                *(const uint4*)(wp2 + (kc * 32 + r) * FDIM + c4);
        }
        __syncthreads();
#pragma unroll
        for (int kt = 0; kt < 4; kt++) {
            int ak = kc * 32 + kt * 8 + tig;
            int bk = kt * 8 + tig;
            unsigned a[4], b[8][2];
            int r = wm + gid;
            a[0] = sAu[r * SAH + ak];
            a[1] = sAu[(r + 8) * SAH + ak];
            a[2] = sAu[r * SAH + ak + 4];
            a[3] = sAu[(r + 8) * SAH + ak + 4];
#pragma unroll
            for (int nt = 0; nt < 8; nt++) {
                int c = wn + nt * 8 + gid;
                b[nt][0] = sBu[bk * SBH + c];
                b[nt][1] = sBu[(bk + 4) * SBH + c];
            }
#pragma unroll
            for (int nt = 0; nt < 8; nt++)
                mma_f16(acc[nt], a, b[nt]);
        }
        __syncthreads();
    }

    // ---- epilogue: h = relu(t2 + b2) -> hout (fp16); stats via shfl-reduce ----
#pragma unroll
    for (int nt = 0; nt < 8; nt++) {
        int c0 = wn + nt * 8 + 2 * tig;
        float bb0 = b2[c0], bb1 = b2[c0 + 1];
        int r0 = m0 + wm + gid, r1 = r0 + 8;
        float s0 = 0.f, s1 = 0.f, q0 = 0.f, q1 = 0.f;
        float v00 = fmaxf(acc[nt][0] + bb0, 0.f);
        float v01 = fmaxf(acc[nt][1] + bb1, 0.f);
        float v10 = fmaxf(acc[nt][2] + bb0, 0.f);
        float v11 = fmaxf(acc[nt][3] + bb1, 0.f);
        if (r0 < M) {
            *(__half2*)(hout + (size_t)r0 * FDIM + c0) = __floats2half2_rn(v00, v01);
            s0 += v00; q0 += v00 * v00;
            s1 += v01; q1 += v01 * v01;
        }
        if (r1 < M) {
            *(__half2*)(hout + (size_t)r1 * FDIM + c0) = __floats2half2_rn(v10, v11);
            s0 += v10; q0 += v10 * v10;
            s1 += v11; q1 += v11 * v11;
        }
        // reduce across gid (lanes tig, tig+4, ..., tig+28)
#pragma unroll
        for (int d = 16; d >= 4; d >>= 1) {
            s0 += __shfl_down_sync(0xffffffffu, s0, d);
            s1 += __shfl_down_sync(0xffffffffu, s1, d);
            q0 += __shfl_down_sync(0xffffffffu, q0, d);
            q1 += __shfl_down_sync(0xffffffffu, q1, d);
        }
        if (gid == 0) {
            atomicAdd(&sred[c0], s0);
            atomicAdd(&sred[c0 + 1], s1);
            atomicAdd(&sred[FDIM + c0], q0);
            atomicAdd(&sred[FDIM + c0 + 1], q1);
        }
    }
    __syncthreads();
    atomicAdd(&g_stats[layer * 2 * FDIM + tid], sred[tid]);
}

// ---------------- pool: segmented sums (batch sorted), 4 blocks/graph -------------
// final h lives in g_ha (layer 3 writes it)
__global__ void k_pool() {
    int g = blockIdx.x >> 2, q = blockIdx.x & 3;
    int t = threadIdx.x;
    int s = g_gstart[g], e = g_gstart[g + 1];
    float acc = 0.f;
    for (int r = s + q; r < e; r += 4) acc += __half2float(g_ha[(size_t)r * FDIM + t]);
    atomicAdd(&g_pool[g * FDIM + t], acc);
}

// ---------------- head: final BN affine + mean + fc1 + relu + fc2 + log_softmax ----
__global__ void k_head(const float* __restrict__ gam, const float* __restrict__ bet,
                       const float* __restrict__ fc1w, const float* __restrict__ fc1b,
                       const float* __restrict__ fc2w, const float* __restrict__ fc2b,
                       float* __restrict__ out) {
    __shared__ float gv[128], r0[128], r1[128];
    int gr = blockIdx.x;
    int t = threadIdx.x;
    int cnt = g_gstart[gr + 1] - g_gstart[gr];

    const float* st = g_stats + 3 * 2 * FDIM;
    const float invN = 1.f / (float)N_NODES;
    float mu = st[t] * invN;
    float var = fmaxf(st[FDIM + t] * invN - mu * mu, 0.f);
    float sc = gam[t] * rsqrtf(var + 1e-5f);
    float sh = bet[t] - mu * sc;

    float gvv = 0.f;
    if (cnt > 0) gvv = sc * (g_pool[gr * FDIM + t] / (float)cnt) + sh;
    gv[t] = gvv;
    __syncthreads();

    float a = fc1b[t];
#pragma unroll 8
    for (int i = 0; i < 128; i++) a += gv[i] * fc1w[i * 128 + t];
    float hv = fmaxf(a, 0.f);
    r0[t] = hv * fc2w[t * 2];
    r1[t] = hv * fc2w[t * 2 + 1];
    __syncthreads();
    for (int s = 64; s > 0; s >>= 1) {
        if (t < s) { r0[t] += r0[t + s]; r1[t] += r1[t + s]; }
        __syncthreads();
    }
    if (t == 0) {
        float l0 = r0[0] + fc2b[0];
        float l1 = r1[0] + fc2b[1];
        float m = fmaxf(l0, l1);
        float lse = m + logf(expf(l0 - m) + expf(l1 - m));
        out[gr * 2] = l0 - lse;
        out[gr * 2 + 1] = l1 - lse;
    }
}

// ---------------- launch ----------------
extern "C" void kernel_launch(void* const* d_in, const int* in_sizes, int n_in,
                              void* d_out, int out_size) {
    const float* x = (const float*)d_in[0];
    const int* ei = (const int*)d_in[1];
    const int* batch = (const int*)d_in[2];
    const float* Ws1 = (const float*)d_in[3];
    const float* bs1 = (const float*)d_in[4];
    const float* Ws2 = (const float*)d_in[5];
    const float* bs2 = (const float*)d_in[6];
    const float* gammas = (const float*)d_in[7];
    const float* betas = (const float*)d_in[8];
    const float* fc1w = (const float*)d_in[9];
    const float* fc1b = (const float*)d_in[10];
    const float* fc2w = (const float*)d_in[11];
    const float* fc2b = (const float*)d_in[12];
    float* out = (float*)d_out;

    const int ZB = (N_NODES + 255) / 256;            // 196
    const int EB = (N_EDGES + 255) / 256;            // 1954
    const int LB = (N_NODES + 63) / 64;              // 782

    k_init<<<ZB, 256>>>(Ws1, Ws2);
    k_fillb<<<EB, 256>>>(ei);
    k_gstart<<<ZB, 256>>>(batch);

    // layer0 gathers from x (fp32) directly; then ping-pong g_hb -> g_ha -> ...
    for (int l = 0; l < NCONV; l++) {
        k_layer<<<LB, 256>>>(x, bs1 + l * FDIM, bs2 + l * FDIM,
                             (l > 0) ? gammas + (l - 1) * FDIM : gammas,
                             (l > 0) ? betas + (l - 1) * FDIM : betas, l);
    }
    k_pool<<<NGRAPH * 4, 128>>>();
    k_head<<<NGRAPH, 128>>>(gammas + 3 * FDIM, betas + 3 * FDIM,
                            fc1w, fc1b, fc2w, fc2b, out);
}

// round 12
// speedup vs baseline: 1.0991x; 1.0991x over previous
#include <cuda_runtime.h>
#include <cuda_fp16.h>
#include <math.h>

#define N_NODES 50000
#define N_EDGES 500000
#define FDIM    128
#define NGRAPH  128
#define NCONV   4
#define DEGCAP  64

// ---------------- scratch (device globals; allocation-free) ----------------
// h arrays have one extra ZERO row (index N_NODES) used as gather padding target.
__device__ __align__(128) __half g_ha[((size_t)N_NODES + 1) * FDIM];
__device__ __align__(128) __half g_hb[((size_t)N_NODES + 1) * FDIM];
__device__ __align__(128) __half2 g_w1p[NCONV * 64 * FDIM];  // packed (k/2, n)
__device__ __align__(128) __half2 g_w2p[NCONV * 64 * FDIM];
__device__ __align__(16)  float g_stats[NCONV * 2 * FDIM];
__device__ __align__(16)  float g_pool[NGRAPH * FDIM];
__device__ int g_cnt[N_NODES];
__device__ int g_adj[(size_t)N_NODES * DEGCAP];
__device__ int g_gstart[NGRAPH + 1];

// ---------------- helpers ----------------
__device__ __forceinline__ void mma_f16(float* c, const unsigned* a, const unsigned* b) {
    asm volatile(
        "mma.sync.aligned.m16n8k16.row.col.f32.f16.f16.f32 "
        "{%0,%1,%2,%3}, {%4,%5,%6,%7}, {%8,%9}, {%0,%1,%2,%3};\n"
        : "+f"(c[0]), "+f"(c[1]), "+f"(c[2]), "+f"(c[3])
        : "r"(a[0]), "r"(a[1]), "r"(a[2]), "r"(a[3]),
          "r"(b[0]), "r"(b[1]));
}

// ---------------- init + W->fp16 pack + zero pad-row ----------------
__global__ void k_init(const float* __restrict__ Ws1, const float* __restrict__ Ws2) {
    int i = blockIdx.x * blockDim.x + threadIdx.x;
    if (i < N_NODES) g_cnt[i] = 0;
    if (i < NCONV * 2 * FDIM) g_stats[i] = 0.f;
    if (i < NGRAPH * FDIM) g_pool[i] = 0.f;
    if (i < FDIM) {
        g_ha[(size_t)N_NODES * FDIM + i] = __float2half(0.f);
        g_hb[(size_t)N_NODES * FDIM + i] = __float2half(0.f);
    }
    if (i < NCONV * 64 * FDIM) {
        int l = i >> 13, rem = i & 8191;
        int kp = rem >> 7, n = rem & 127;
        const float* w1 = Ws1 + l * FDIM * FDIM;
        const float* w2 = Ws2 + l * FDIM * FDIM;
        g_w1p[i] = __floats2half2_rn(w1[(2 * kp) * 128 + n], w1[(2 * kp + 1) * 128 + n]);
        g_w2p[i] = __floats2half2_rn(w2[(2 * kp) * 128 + n], w2[(2 * kp + 1) * 128 + n]);
    }
}

// ---------------- adjacency buckets ----------------
__global__ void k_fillb(const int* __restrict__ ei) {
    int e = blockIdx.x * blockDim.x + threadIdx.x;
    if (e < N_EDGES) {
        int d = ei[N_EDGES + e];
        int pos = atomicAdd(&g_cnt[d], 1);
        if (pos < DEGCAP) g_adj[(size_t)d * DEGCAP + pos] = ei[e];
    }
}

// ---------------- pad buckets to multiple of 8 with the zero-row index ----------
__global__ void k_pad() {
    int i = blockIdx.x * blockDim.x + threadIdx.x;
    if (i >= N_NODES) return;
    int deg = g_cnt[i];
    if (deg > DEGCAP) deg = DEGCAP;
    int dpad = (deg + 7) & ~7;
    for (int p = deg; p < dpad; p++) g_adj[(size_t)i * DEGCAP + p] = N_NODES;
}

// ---------------- graph segment starts (batch is sorted) ----------------
__global__ void k_gstart(const int* __restrict__ batch) {
    int i = blockIdx.x * blockDim.x + threadIdx.x;
    if (i >= N_NODES) return;
    int b = batch[i];
    int bp = (i == 0) ? -1 : batch[i - 1];
    for (int g = bp + 1; g <= b; g++) g_gstart[g] = i;
    if (i == N_NODES - 1)
        for (int g = b + 1; g <= NGRAPH; g++) g_gstart[g] = N_NODES;
}

// ====== fused layer (fp16): BN-affine + agg + GEMM1+relu + GEMM2+relu + stats ======
// 64-row tile, 256 threads = 8 warps (warp grid 4x2, warp tile 16x64), fp16 MMA k16.
// sA = 64 x 68 half2 (z tile, then t1); sB = 32 x 136 half2 (W 64-k chunk). 35.8 KB.
// 4 CTAs/SM, 64 regs. Layers>=1: padded branch-free gather (zero-row padding).
#define SAH 68
#define SBH 136

__global__ __launch_bounds__(256, 4)
void k_layer(const float* __restrict__ xext,
             const float* __restrict__ b1, const float* __restrict__ b2,
             const float* __restrict__ gam, const float* __restrict__ bet,
             int layer) {
    __shared__ __half2 sA2[64 * SAH];
    __shared__ __half2 sB2[32 * SBH];
    __shared__ float sred[2 * FDIM];

    const __half* hin = (layer & 1) ? g_hb : g_ha;
    __half* hout = (layer & 1) ? g_ha : g_hb;
    const unsigned* sAu = (const unsigned*)sA2;
    const unsigned* sBu = (const unsigned*)sB2;
    const int M = N_NODES;

    int tid = threadIdx.x, wid = tid >> 5, lane = tid & 31;
    int gid = lane >> 2, tig = lane & 3;
    int wm = (wid & 3) * 16, wn = (wid >> 2) * 64;
    int m0 = blockIdx.x * 64;

    sred[tid] = 0.f;

    // per-lane BN affine (cols lane*4 .. +3)
    float sc0 = 1.f, sc1 = 1.f, sc2 = 1.f, sc3 = 1.f;
    float sh0 = 0.f, sh1 = 0.f, sh2 = 0.f, sh3 = 0.f;
    if (layer > 0) {
        const float* st = g_stats + (layer - 1) * 2 * FDIM;
        const float invN = 1.f / (float)N_NODES;
        int c = lane * 4;
        float mu0 = st[c] * invN, v0 = fmaxf(st[FDIM + c] * invN - mu0 * mu0, 0.f);
        sc0 = gam[c] * rsqrtf(v0 + 1e-5f); sh0 = bet[c] - mu0 * sc0;
        float mu1 = st[c + 1] * invN, v1 = fmaxf(st[FDIM + c + 1] * invN - mu1 * mu1, 0.f);
        sc1 = gam[c + 1] * rsqrtf(v1 + 1e-5f); sh1 = bet[c + 1] - mu1 * sc1;
        float mu2 = st[c + 2] * invN, v2 = fmaxf(st[FDIM + c + 2] * invN - mu2 * mu2, 0.f);
        sc2 = gam[c + 2] * rsqrtf(v2 + 1e-5f); sh2 = bet[c + 2] - mu2 * sc2;
        float mu3 = st[c + 3] * invN, v3 = fmaxf(st[FDIM + c + 3] * invN - mu3 * mu3, 0.f);
        sc3 = gam[c + 3] * rsqrtf(v3 + 1e-5f); sh3 = bet[c + 3] - mu3 * sc3;
    }

    // ---- aggregation: each warp owns 8 rows ----
    for (int rr = 0; rr < 8; rr++) {
        int r = wid * 8 + rr;
        int node = m0 + r;
        __half2 o0 = __floats2half2_rn(0.f, 0.f), o1 = o0;
        if (node < M) {
            float4 acc;
            int deg = g_cnt[node];
            if (deg > DEGCAP) deg = DEGCAP;
            const int* adj = g_adj + (size_t)node * DEGCAP;
            if (layer == 0) {
                // masked fp32 gather from x (x cannot be padded)
                int dm1 = deg - 1;
                acc = ((const float4*)(xext + (size_t)node * FDIM))[lane];
                for (int k = 0; k < deg; k += 8) {
                    int j[8]; float mk[8];
#pragma unroll
                    for (int u = 0; u < 8; u++) {
                        int idx = k + u;
                        j[u] = adj[idx < dm1 ? idx : dm1];
                        mk[u] = (idx < deg) ? 1.f : 0.f;
                    }
                    float4 v[8];
#pragma unroll
                    for (int u = 0; u < 8; u++)
                        v[u] = ((const float4*)(xext + (size_t)j[u] * FDIM))[lane];
#pragma unroll
                    for (int u = 0; u < 8; u++) {
                        acc.x += mk[u] * v[u].x;
                        acc.y += mk[u] * v[u].y;
                        acc.z += mk[u] * v[u].z;
                        acc.w += mk[u] * v[u].w;
                    }
                }
            } else {
                // branch-free padded fp16 gather (padding hits the zero row)
                uint2 sv = *(const uint2*)(hin + (size_t)node * FDIM + lane * 4);
                float2 p = __half22float2(*(__half2*)&sv.x);
                float2 q = __half22float2(*(__half2*)&sv.y);
                acc = make_float4(p.x, p.y, q.x, q.y);
                int dpad = (deg + 7) & ~7;
                for (int k = 0; k < dpad; k += 8) {
                    int j[8];
#pragma unroll
                    for (int u = 0; u < 8; u++) j[u] = adj[k + u];
                    uint2 v[8];
#pragma unroll
                    for (int u = 0; u < 8; u++)
                        v[u] = *(const uint2*)(hin + (size_t)j[u] * FDIM + lane * 4);
#pragma unroll
                    for (int u = 0; u < 8; u++) {
                        float2 a = __half22float2(*(__half2*)&v[u].x);
                        float2 b = __half22float2(*(__half2*)&v[u].y);
                        acc.x += a.x;
                        acc.y += a.y;
                        acc.z += b.x;
                        acc.w += b.y;
                    }
                }
                float dp1 = (float)(deg + 1);
                acc.x = sc0 * acc.x + dp1 * sh0;
                acc.y = sc1 * acc.y + dp1 * sh1;
                acc.z = sc2 * acc.z + dp1 * sh2;
                acc.w = sc3 * acc.w + dp1 * sh3;
            }
            o0 = __floats2half2_rn(acc.x, acc.y);
            o1 = __floats2half2_rn(acc.z, acc.w);
        }
        __half2 pair[2] = {o0, o1};
        *(uint2*)(sA2 + r * SAH + lane * 2) = *(uint2*)pair;
    }
    __syncthreads();

    // ---- GEMM1: t1 = z @ W1 ----
    const __half2* wp1 = g_w1p + layer * 64 * FDIM;
    float acc[8][4];
#pragma unroll
    for (int nt = 0; nt < 8; nt++)
#pragma unroll
        for (int i = 0; i < 4; i++) acc[nt][i] = 0.f;

#pragma unroll
    for (int kc = 0; kc < 2; kc++) {
#pragma unroll
        for (int i = 0; i < 4; i++) {
            int slot = tid + i * 256;              // 1024 uint4 slots
            int r = slot >> 5, c4 = (slot & 31) << 2;
            *(uint4*)(sB2 + r * SBH + c4) =
                *(const uint4*)(wp1 + (kc * 32 + r) * FDIM + c4);
        }
        __syncthreads();
#pragma unroll
        for (int kt = 0; kt < 4; kt++) {
            int ak = kc * 32 + kt * 8 + tig;       // half2 k-offset in sA
            int bk = kt * 8 + tig;                 // half2 k-row in sB chunk
            unsigned a[4], b[8][2];
            int r = wm + gid;
            a[0] = sAu[r * SAH + ak];
            a[1] = sAu[(r + 8) * SAH + ak];
            a[2] = sAu[r * SAH + ak + 4];
            a[3] = sAu[(r + 8) * SAH + ak + 4];
#pragma unroll
            for (int nt = 0; nt < 8; nt++) {
                int c = wn + nt * 8 + gid;
                b[nt][0] = sBu[bk * SBH + c];
                b[nt][1] = sBu[(bk + 4) * SBH + c];
            }
#pragma unroll
            for (int nt = 0; nt < 8; nt++)
                mma_f16(acc[nt], a, b[nt]);
        }
        __syncthreads();
    }

    // ---- t1 = relu(acc + b1) back into sA (fp16) ----
#pragma unroll
    for (int nt = 0; nt < 8; nt++) {
        int c0 = wn + nt * 8 + 2 * tig;
        float bb0 = b1[c0], bb1 = b1[c0 + 1];
        int r0 = wm + gid, r1 = r0 + 8;
        int ci = (wn >> 1) + nt * 4 + tig;
        sA2[r0 * SAH + ci] = __floats2half2_rn(fmaxf(acc[nt][0] + bb0, 0.f),
                                               fmaxf(acc[nt][1] + bb1, 0.f));
        sA2[r1 * SAH + ci] = __floats2half2_rn(fmaxf(acc[nt][2] + bb0, 0.f),
                                               fmaxf(acc[nt][3] + bb1, 0.f));
    }
#pragma unroll
    for (int nt = 0; nt < 8; nt++)
#pragma unroll
        for (int i = 0; i < 4; i++) acc[nt][i] = 0.f;

    // ---- GEMM2: t2 = t1 @ W2 (chunk-stage sync covers the sA writes) ----
    const __half2* wp2 = g_w2p + layer * 64 * FDIM;
#pragma unroll
    for (int kc = 0; kc < 2; kc++) {
#pragma unroll
        for (int i = 0; i < 4; i++) {
            int slot = tid + i * 256;
            int r = slot >> 5, c4 = (slot & 31) << 2;
            *(uint4*)(sB2 + r * SBH + c4) =
                *(const uint4*)(wp2 + (kc * 32 + r) * FDIM + c4);
        }
        __syncthreads();
#pragma unroll
        for (int kt = 0; kt < 4; kt++) {
            int ak = kc * 32 + kt * 8 + tig;
            int bk = kt * 8 + tig;
            unsigned a[4], b[8][2];
            int r = wm + gid;
            a[0] = sAu[r * SAH + ak];
            a[1] = sAu[(r + 8) * SAH + ak];
            a[2] = sAu[r * SAH + ak + 4];
            a[3] = sAu[(r + 8) * SAH + ak + 4];
#pragma unroll
            for (int nt = 0; nt < 8; nt++) {
                int c = wn + nt * 8 + gid;
                b[nt][0] = sBu[bk * SBH + c];
                b[nt][1] = sBu[(bk + 4) * SBH + c];
            }
#pragma unroll
            for (int nt = 0; nt < 8; nt++)
                mma_f16(acc[nt], a, b[nt]);
        }
        __syncthreads();
    }

    // ---- epilogue: h = relu(t2 + b2) -> hout (fp16); stats via shfl-reduce ----
#pragma unroll
    for (int nt = 0; nt < 8; nt++) {
        int c0 = wn + nt * 8 + 2 * tig;
        float bb0 = b2[c0], bb1 = b2[c0 + 1];
        int r0 = m0 + wm + gid, r1 = r0 + 8;
        float s0 = 0.f, s1 = 0.f, q0 = 0.f, q1 = 0.f;
        float v00 = fmaxf(acc[nt][0] + bb0, 0.f);
        float v01 = fmaxf(acc[nt][1] + bb1, 0.f);
        float v10 = fmaxf(acc[nt][2] + bb0, 0.f);
        float v11 = fmaxf(acc[nt][3] + bb1, 0.f);
        if (r0 < M) {
            *(__half2*)(hout + (size_t)r0 * FDIM + c0) = __floats2half2_rn(v00, v01);
            s0 += v00; q0 += v00 * v00;
            s1 += v01; q1 += v01 * v01;
        }
        if (r1 < M) {
            *(__half2*)(hout + (size_t)r1 * FDIM + c0) = __floats2half2_rn(v10, v11);
            s0 += v10; q0 += v10 * v10;
            s1 += v11; q1 += v11 * v11;
        }
        // reduce across gid (lanes tig, tig+4, ..., tig+28)
#pragma unroll
        for (int d = 16; d >= 4; d >>= 1) {
            s0 += __shfl_down_sync(0xffffffffu, s0, d);
            s1 += __shfl_down_sync(0xffffffffu, s1, d);
            q0 += __shfl_down_sync(0xffffffffu, q0, d);
            q1 += __shfl_down_sync(0xffffffffu, q1, d);
        }
        if (gid == 0) {
            atomicAdd(&sred[c0], s0);
            atomicAdd(&sred[c0 + 1], s1);
            atomicAdd(&sred[FDIM + c0], q0);
            atomicAdd(&sred[FDIM + c0 + 1], q1);
        }
    }
    __syncthreads();
    atomicAdd(&g_stats[layer * 2 * FDIM + tid], sred[tid]);
}

// ---------------- pool: segmented sums (batch sorted), 4 blocks/graph -------------
// final h lives in g_ha (layer 3 writes it)
__global__ void k_pool() {
    int g = blockIdx.x >> 2, q = blockIdx.x & 3;
    int t = threadIdx.x;
    int s = g_gstart[g], e = g_gstart[g + 1];
    float acc = 0.f;
    for (int r = s + q; r < e; r += 4) acc += __half2float(g_ha[(size_t)r * FDIM + t]);
    atomicAdd(&g_pool[g * FDIM + t], acc);
}

// ---------------- head: final BN affine + mean + fc1 + relu + fc2 + log_softmax ----
__global__ void k_head(const float* __restrict__ gam, const float* __restrict__ bet,
                       const float* __restrict__ fc1w, const float* __restrict__ fc1b,
                       const float* __restrict__ fc2w, const float* __restrict__ fc2b,
                       float* __restrict__ out) {
    __shared__ float gv[128], r0[128], r1[128];
    int gr = blockIdx.x;
    int t = threadIdx.x;
    int cnt = g_gstart[gr + 1] - g_gstart[gr];

    const float* st = g_stats + 3 * 2 * FDIM;
    const float invN = 1.f / (float)N_NODES;
    float mu = st[t] * invN;
    float var = fmaxf(st[FDIM + t] * invN - mu * mu, 0.f);
    float sc = gam[t] * rsqrtf(var + 1e-5f);
    float sh = bet[t] - mu * sc;

    float gvv = 0.f;
    if (cnt > 0) gvv = sc * (g_pool[gr * FDIM + t] / (float)cnt) + sh;
    gv[t] = gvv;
    __syncthreads();

    float a = fc1b[t];
#pragma unroll 8
    for (int i = 0; i < 128; i++) a += gv[i] * fc1w[i * 128 + t];
    float hv = fmaxf(a, 0.f);
    r0[t] = hv * fc2w[t * 2];
    r1[t] = hv * fc2w[t * 2 + 1];
    __syncthreads();
    for (int s = 64; s > 0; s >>= 1) {
        if (t < s) { r0[t] += r0[t + s]; r1[t] += r1[t + s]; }
        __syncthreads();
    }
    if (t == 0) {
        float l0 = r0[0] + fc2b[0];
        float l1 = r1[0] + fc2b[1];
        float m = fmaxf(l0, l1);
        float lse = m + logf(expf(l0 - m) + expf(l1 - m));
        out[gr * 2] = l0 - lse;
        out[gr * 2 + 1] = l1 - lse;
    }
}

// ---------------- launch ----------------
extern "C" void kernel_launch(void* const* d_in, const int* in_sizes, int n_in,
                              void* d_out, int out_size) {
    const float* x = (const float*)d_in[0];
    const int* ei = (const int*)d_in[1];
    const int* batch = (const int*)d_in[2];
    const float* Ws1 = (const float*)d_in[3];
    const float* bs1 = (const float*)d_in[4];
    const float* Ws2 = (const float*)d_in[5];
    const float* bs2 = (const float*)d_in[6];
    const float* gammas = (const float*)d_in[7];
    const float* betas = (const float*)d_in[8];
    const float* fc1w = (const float*)d_in[9];
    const float* fc1b = (const float*)d_in[10];
    const float* fc2w = (const float*)d_in[11];
    const float* fc2b = (const float*)d_in[12];
    float* out = (float*)d_out;

    const int ZB = (N_NODES + 255) / 256;            // 196
    const int EB = (N_EDGES + 255) / 256;            // 1954
    const int LB = (N_NODES + 63) / 64;              // 782

    k_init<<<ZB, 256>>>(Ws1, Ws2);
    k_fillb<<<EB, 256>>>(ei);
    k_pad<<<ZB, 256>>>();
    k_gstart<<<ZB, 256>>>(batch);

    // layer0 gathers from x (fp32) directly; then ping-pong g_hb -> g_ha -> ...
    for (int l = 0; l < NCONV; l++) {
        k_layer<<<LB, 256>>>(x, bs1 + l * FDIM, bs2 + l * FDIM,
                             (l > 0) ? gammas + (l - 1) * FDIM : gammas,
                             (l > 0) ? betas + (l - 1) * FDIM : betas, l);
    }
    k_pool<<<NGRAPH * 4, 128>>>();
    k_head<<<NGRAPH, 128>>>(gammas + 3 * FDIM, betas + 3 * FDIM,
                            fc1w, fc1b, fc2w, fc2b, out);
}